// round 2
// baseline (speedup 1.0000x reference)
#include <cuda_runtime.h>
#include <math.h>

// SimDiff: right[f,i] = cos(x[f,i], x[f+1,i+1]),  i in [0, tpf-2]
//          down [f,i] = cos(x[f,i], x[f+1,i+W]),  i in [0, tpf-W-1]
// else -1.  Shapes fixed by setup_inputs: frames=64, H=23, W=24, D=1152.

#define FRAMES 64
#define HEIGHT 23
#define WIDTH  24
#define TPF    (HEIGHT * WIDTH)   // 552
#define HID    1152
#define VALID  (FRAMES - 1)       // interval = 1
#define TOTAL  (FRAMES * TPF)     // 35328
#define EPS    1e-8f

__global__ void __launch_bounds__(256, 8)
simdiff_kernel(const float* __restrict__ x, float* __restrict__ out) {
    const int gwarp = (blockIdx.x * blockDim.x + threadIdx.x) >> 5;
    const int lane  = threadIdx.x & 31;
    if (gwarp >= TOTAL) return;

    const int f = gwarp / TPF;
    const int i = gwarp - f * TPF;

    const bool do_r = (f < VALID) && (i < TPF - 1);
    const bool do_d = (f < VALID) && (i < TPF - WIDTH);

    float right = -1.0f, down = -1.0f;

    if (do_r || do_d) {
        const float4* __restrict__ a =
            (const float4*)(x + (size_t)(f * TPF + i) * HID);
        // Guard invalid neighbors by aliasing to 'a' (no OOB, result unused).
        const float4* __restrict__ b = do_r
            ? (const float4*)(x + (size_t)((f + 1) * TPF + i + 1) * HID) : a;
        const float4* __restrict__ c = do_d
            ? (const float4*)(x + (size_t)((f + 1) * TPF + i + WIDTH) * HID) : a;

        float dab = 0.f, dac = 0.f, naa = 0.f, nbb = 0.f, ncc = 0.f;

        // HID/4 = 288 float4 per row; 288/32 = 9 per lane, coalesced.
        #pragma unroll
        for (int j = 0; j < HID / 4 / 32; ++j) {
            const int k = lane + j * 32;
            float4 av = a[k];
            float4 bv = b[k];
            float4 cv = c[k];
            dab = fmaf(av.x, bv.x, dab); dab = fmaf(av.y, bv.y, dab);
            dab = fmaf(av.z, bv.z, dab); dab = fmaf(av.w, bv.w, dab);
            dac = fmaf(av.x, cv.x, dac); dac = fmaf(av.y, cv.y, dac);
            dac = fmaf(av.z, cv.z, dac); dac = fmaf(av.w, cv.w, dac);
            naa = fmaf(av.x, av.x, naa); naa = fmaf(av.y, av.y, naa);
            naa = fmaf(av.z, av.z, naa); naa = fmaf(av.w, av.w, naa);
            nbb = fmaf(bv.x, bv.x, nbb); nbb = fmaf(bv.y, bv.y, nbb);
            nbb = fmaf(bv.z, bv.z, nbb); nbb = fmaf(bv.w, bv.w, nbb);
            ncc = fmaf(cv.x, cv.x, ncc); ncc = fmaf(cv.y, cv.y, ncc);
            ncc = fmaf(cv.z, cv.z, ncc); ncc = fmaf(cv.w, cv.w, ncc);
        }

        // Warp tree-reduce 5 scalars.
        #pragma unroll
        for (int off = 16; off > 0; off >>= 1) {
            dab += __shfl_xor_sync(0xFFFFFFFFu, dab, off);
            dac += __shfl_xor_sync(0xFFFFFFFFu, dac, off);
            naa += __shfl_xor_sync(0xFFFFFFFFu, naa, off);
            nbb += __shfl_xor_sync(0xFFFFFFFFu, nbb, off);
            ncc += __shfl_xor_sync(0xFFFFFFFFu, ncc, off);
        }

        const float na = fmaxf(sqrtf(naa), EPS);
        if (do_r) {
            const float nb = fmaxf(sqrtf(nbb), EPS);
            right = dab / (na * nb);
        }
        if (do_d) {
            const float nc = fmaxf(sqrtf(ncc), EPS);
            down = dac / (na * nc);
        }
    }

    if (lane == 0) {
        out[gwarp]         = right;
        out[TOTAL + gwarp] = down;
    }
}

extern "C" void kernel_launch(void* const* d_in, const int* in_sizes, int n_in,
                              void* d_out, int out_size) {
    const float* x = (const float*)d_in[0];
    float* out = (float*)d_out;

    // One warp per output position; 8 warps per 256-thread block.
    const int warps_per_block = 256 / 32;
    const int grid = (TOTAL + warps_per_block - 1) / warps_per_block; // 4416
    simdiff_kernel<<<grid, 256>>>(x, out);
}

// round 3
// speedup vs baseline: 1.0420x; 1.0420x over previous
#include <cuda_runtime.h>
#include <math.h>

// SimDiff: right[f,i] = cos(x[f,i], x[f+1,i+1]),  i in [0, tpf-2]
//          down [f,i] = cos(x[f,i], x[f+1,i+W]),  i in [0, tpf-W-1]
// else -1.  Shapes fixed by setup_inputs: frames=64, H=23, W=24, D=1152.

#define FRAMES 64
#define HEIGHT 23
#define WIDTH  24
#define TPF    (HEIGHT * WIDTH)   // 552
#define HID    1152
#define VALID  (FRAMES - 1)       // interval = 1
#define TOTAL  (FRAMES * TPF)     // 35328
#define EPS    1e-8f

// 9 float4 per lane per row; process in 3 chunks of 3 so each chunk issues
// 9 independent float4 loads (36 regs in flight) before any FMA.
#define ITERS  (HID / 4 / 32)     // 9
#define CHUNK  3

__global__ void __launch_bounds__(256, 4)
simdiff_kernel(const float* __restrict__ x, float* __restrict__ out) {
    const int gwarp = (blockIdx.x * blockDim.x + threadIdx.x) >> 5;
    const int lane  = threadIdx.x & 31;
    if (gwarp >= TOTAL) return;

    const int f = gwarp / TPF;
    const int i = gwarp - f * TPF;

    const bool do_r = (f < VALID) && (i < TPF - 1);
    const bool do_d = (f < VALID) && (i < TPF - WIDTH);

    float right = -1.0f, down = -1.0f;

    if (do_r || do_d) {
        const float4* __restrict__ a =
            (const float4*)(x + (size_t)(f * TPF + i) * HID) + lane;
        // Guard invalid neighbors by aliasing to 'a' (no OOB, result unused).
        const float4* __restrict__ b = (do_r
            ? (const float4*)(x + (size_t)((f + 1) * TPF + i + 1) * HID)
            : (const float4*)(x + (size_t)(f * TPF + i) * HID)) + lane;
        const float4* __restrict__ c = (do_d
            ? (const float4*)(x + (size_t)((f + 1) * TPF + i + WIDTH) * HID)
            : (const float4*)(x + (size_t)(f * TPF + i) * HID)) + lane;

        float dab = 0.f, dac = 0.f, naa = 0.f, nbb = 0.f, ncc = 0.f;

        #pragma unroll
        for (int ch = 0; ch < ITERS / CHUNK; ++ch) {
            float4 av[CHUNK], bv[CHUNK], cv[CHUNK];
            // Issue all 9 loads of this chunk before consuming any.
            #pragma unroll
            for (int u = 0; u < CHUNK; ++u) {
                const int k = (ch * CHUNK + u) * 32;
                av[u] = a[k];
                bv[u] = b[k];
                cv[u] = c[k];
            }
            #pragma unroll
            for (int u = 0; u < CHUNK; ++u) {
                dab = fmaf(av[u].x, bv[u].x, dab); dab = fmaf(av[u].y, bv[u].y, dab);
                dab = fmaf(av[u].z, bv[u].z, dab); dab = fmaf(av[u].w, bv[u].w, dab);
                dac = fmaf(av[u].x, cv[u].x, dac); dac = fmaf(av[u].y, cv[u].y, dac);
                dac = fmaf(av[u].z, cv[u].z, dac); dac = fmaf(av[u].w, cv[u].w, dac);
                naa = fmaf(av[u].x, av[u].x, naa); naa = fmaf(av[u].y, av[u].y, naa);
                naa = fmaf(av[u].z, av[u].z, naa); naa = fmaf(av[u].w, av[u].w, naa);
                nbb = fmaf(bv[u].x, bv[u].x, nbb); nbb = fmaf(bv[u].y, bv[u].y, nbb);
                nbb = fmaf(bv[u].z, bv[u].z, nbb); nbb = fmaf(bv[u].w, bv[u].w, nbb);
                ncc = fmaf(cv[u].x, cv[u].x, ncc); ncc = fmaf(cv[u].y, cv[u].y, ncc);
                ncc = fmaf(cv[u].z, cv[u].z, ncc); ncc = fmaf(cv[u].w, cv[u].w, ncc);
            }
        }

        // Warp tree-reduce 5 scalars.
        #pragma unroll
        for (int off = 16; off > 0; off >>= 1) {
            dab += __shfl_xor_sync(0xFFFFFFFFu, dab, off);
            dac += __shfl_xor_sync(0xFFFFFFFFu, dac, off);
            naa += __shfl_xor_sync(0xFFFFFFFFu, naa, off);
            nbb += __shfl_xor_sync(0xFFFFFFFFu, nbb, off);
            ncc += __shfl_xor_sync(0xFFFFFFFFu, ncc, off);
        }

        const float na = fmaxf(sqrtf(naa), EPS);
        if (do_r) {
            const float nb = fmaxf(sqrtf(nbb), EPS);
            right = dab / (na * nb);
        }
        if (do_d) {
            const float nc = fmaxf(sqrtf(ncc), EPS);
            down = dac / (na * nc);
        }
    }

    if (lane == 0) {
        out[gwarp]         = right;
        out[TOTAL + gwarp] = down;
    }
}

extern "C" void kernel_launch(void* const* d_in, const int* in_sizes, int n_in,
                              void* d_out, int out_size) {
    const float* x = (const float*)d_in[0];
    float* out = (float*)d_out;

    const int warps_per_block = 256 / 32;
    const int grid = (TOTAL + warps_per_block - 1) / warps_per_block; // 4416
    simdiff_kernel<<<grid, 256>>>(x, out);
}